// round 15
// baseline (speedup 1.0000x reference)
#include <cuda_runtime.h>

#define NN 50000
#define NE 800000
#define H 128
#define ED 32
#define BN_EPS 1e-5f
#define RES_SCALE 0.1f

// ---------------- scratch (device globals; allocation-free) ----------------
__device__ __align__(16) float g_h[NN * H];
__device__ __align__(16) float g_z[NN * H];
__device__ __align__(16) float g_t[NN * H];
__device__ __align__(16) float g_z2[NN * H];
__device__ int g_src[NE];
__device__ int g_dstv[NE];
__device__ int g_eid[NE];
__device__ int g_ssort[NE];
__device__ int g_dsort[NE];
__device__ int g_cnt[NN];
__device__ int g_cursor[NN];
__device__ int g_ready;
__device__ int g_running;
__device__ __align__(16) float g_colsum[H];
__device__ __align__(16) float g_colsq[H];

__device__ __forceinline__ unsigned to_tf32(float f) {
    unsigned u;
    asm("cvt.rna.tf32.f32 %0, %1;" : "=r"(u) : "f"(f));
    return u;
}

#define MMA_TF32(D, A0, A1, A2, A3, B0, B1)                                   \
    asm("mma.sync.aligned.m16n8k8.row.col.f32.tf32.tf32.f32 "                 \
        "{%0,%1,%2,%3}, {%4,%5,%6,%7}, {%8,%9}, {%0,%1,%2,%3};"               \
        : "+f"(D[0]), "+f"(D[1]), "+f"(D[2]), "+f"(D[3])                      \
        : "r"(A0), "r"(A1), "r"(A2), "r"(A3), "r"(B0), "r"(B1))

// ---------------- fused CSR-count + h/z init --------------------------------
__global__ void k_prepinit(const float* __restrict__ x, const int* __restrict__ p) {
    int tid = threadIdx.x;
    int gid = blockIdx.x * 256 + tid;
    if (gid < NE) {
        int lane = tid & 31;
        int hi = p[2 * lane + 1] | p[2 * (lane + 32) + 1];
        bool i64 = (__ballot_sync(0xffffffffu, hi != 0) == 0);
        int s, d;
        if (i64) {
            const long long* q = (const long long*)p;
            s = (int)q[gid];
            d = (int)q[NE + gid];
        } else {
            s = p[gid];
            d = p[NE + gid];
        }
        g_src[gid] = s;
        g_dstv[gid] = d;
        atomicAdd(&g_cnt[d], 1);
    }
    if (gid < NN * H / 4) {
        float4 v = ((const float4*)x)[gid];
        ((float4*)g_h)[gid] = v;
        ((float4*)g_z)[gid] = v;
    }
}

// ---------------- single-pass decoupled chained scan ------------------------
__global__ void __launch_bounds__(1024) k_scan() {
    __shared__ int ws[32];
    __shared__ int sbase;
    int tid = threadIdx.x, lane = tid & 31, wid = tid >> 5;
    int i = blockIdx.x * 1024 + tid;
    int v = (i < NN) ? g_cnt[i] : 0;
    int s = v;
#pragma unroll
    for (int o = 1; o < 32; o <<= 1) {
        int t = __shfl_up_sync(0xffffffffu, s, o);
        if (lane >= o) s += t;
    }
    if (lane == 31) ws[wid] = s;
    __syncthreads();
    if (wid == 0) {
        int t = ws[lane];
#pragma unroll
        for (int o = 1; o < 32; o <<= 1) {
            int u = __shfl_up_sync(0xffffffffu, t, o);
            if (lane >= o) t += u;
        }
        ws[lane] = t;
    }
    __syncthreads();
    if (tid == 0) {
        int total = ws[31];
        int b = blockIdx.x;
        while (*(volatile int*)&g_ready != b) {
        }
        int base = *(volatile int*)&g_running;
        *(volatile int*)&g_running = base + total;
        __threadfence();
        *(volatile int*)&g_ready = b + 1;
        sbase = base;
    }
    __syncthreads();
    int excl = s - v + (wid > 0 ? ws[wid - 1] : 0) + sbase;
    if (i < NN) g_cursor[i] = excl;
}

// ---------------- light scatter: CSR index arrays only ----------------------
__global__ void k_scat() {
    int e = blockIdx.x * 256 + threadIdx.x;
    if (e == 0) {
        g_ready = 0;
        g_running = 0;
    }
    if (e < NN) g_cnt[e] = 0;
    if (e >= NE) return;
    int d = g_dstv[e];
    int pos = atomicAdd(&g_cursor[d], 1);
    g_eid[pos] = e;
    g_ssort[pos] = g_src[e];
    g_dsort[pos] = d;
}

// ---------------- fused edge-linear + aggregate ------------------------------
// Quarter-staged, conflict-free:
//  - Ws stored xor-swizzled (n ^ ((k&3)<<3)) -> B-fragment LDS conflict-free
//  - per-warp stage strip 16x36 (quarter of cols at a time), overlaid on As
//  - smem = max(As,stage) 4608 + Ws 4224 = 8832 words = 35.3KB -> 6 blocks/SM
#define EAGG_SMEM ((4608 + 32 * 132) * 4)
__global__ void __launch_bounds__(256, 6) k_eagg(const float* __restrict__ ea,
                                                 const float* __restrict__ We,
                                                 const float* __restrict__ be) {
    extern __shared__ float smf[];
    unsigned* As = (unsigned*)smf;          // phase 1: 128 x 36
    float* stage = smf;                     // phase 2: per-warp 16 x 36
    unsigned* Ws = (unsigned*)smf + 4608;   // 32 x 132, xor-swizzled

    int tid = threadIdx.x;
    int lane = tid & 31;
    int w = tid >> 5;
    size_t tile0 = (size_t)blockIdx.x * 128;

    for (int i = tid; i < 1024; i += 256) {  // A: 128 CSR rows x 32 feats
        int r = i >> 3, c4 = i & 7;
        size_t j = tile0 + r;
        float4 v = make_float4(0.f, 0.f, 0.f, 0.f);
        if (j < NE) {
            int e = g_eid[j];
            v = *(const float4*)(ea + (size_t)e * ED + c4 * 4);
        }
        unsigned* dst = As + r * 36 + c4 * 4;
        dst[0] = to_tf32(v.x); dst[1] = to_tf32(v.y);
        dst[2] = to_tf32(v.z); dst[3] = to_tf32(v.w);
    }
    for (int i = tid; i < 1024; i += 256) {  // W: 32 x 128, swizzled store
        int k = i >> 5, c4 = i & 31;
        float4 v = *(const float4*)(We + (size_t)k * H + c4 * 4);
        unsigned* dst = Ws + k * 132 + ((c4 * 4) ^ ((k & 3) << 3));
        dst[0] = to_tf32(v.x); dst[1] = to_tf32(v.y);
        dst[2] = to_tf32(v.z); dst[3] = to_tf32(v.w);
    }
    __syncthreads();

    int g = lane >> 2;
    int r = lane & 3;
    int row_s = w * 16;

    unsigned a[4][4];
#pragma unroll
    for (int ks = 0; ks < 4; ks++) {
        int k0 = ks * 8;
        a[ks][0] = As[(row_s + g) * 36 + k0 + r];
        a[ks][1] = As[(row_s + g + 8) * 36 + k0 + r];
        a[ks][2] = As[(row_s + g) * 36 + k0 + r + 4];
        a[ks][3] = As[(row_s + g + 8) * 36 + k0 + r + 4];
    }
    __syncthreads();  // all As reads done; stage may now overwrite region0

    // batched index preload: lanes 0-15 -> ssort, lanes 16-31 -> dsort
    size_t j0 = tile0 + (size_t)w * 16;
    int myidx;
    if (lane < 16) {
        size_t j = j0 + lane;
        myidx = (j < NE) ? g_ssort[j] : 0;
    } else {
        size_t j = j0 + lane - 16;
        myidx = (j < NE) ? g_dsort[j] : -1;
    }

    float* wst = stage + w * 576;  // warp-private 16 x 36 strip

#pragma unroll
    for (int q = 0; q < 4; q++) {
        // compute 4 nt fragments for this column quarter, stage warp-locally
#pragma unroll
        for (int ntl = 0; ntl < 4; ntl++) {
            int nt = q * 4 + ntl;
            int n0 = nt * 8;
            float d[4];
            float2 bb = *(const float2*)(be + n0 + 2 * r);
            d[0] = bb.x; d[1] = bb.y; d[2] = bb.x; d[3] = bb.y;
            int nsw = (n0 + g) ^ (r << 3);  // xor-unswizzle (k&3 == r)
#pragma unroll
            for (int ks = 0; ks < 4; ks++) {
                int k0 = ks * 8;
                unsigned b0 = Ws[(k0 + r) * 132 + nsw];
                unsigned b1 = Ws[(k0 + 4 + r) * 132 + nsw];
                MMA_TF32(d, a[ks][0], a[ks][1], a[ks][2], a[ks][3], b0, b1);
            }
            int lc = ntl * 8 + 2 * r;
            *(float2*)(wst + g * 36 + lc) = make_float2(d[0], d[1]);
            *(float2*)(wst + (g + 8) * 36 + lc) = make_float2(d[2], d[3]);
        }
        __syncwarp();

        // aggregate this quarter: lane owns 1 col
        int c0 = q * 32 + lane;
        float acc = 0.f;
#pragma unroll
        for (int i = 0; i < 16; i++) {
            bool valid = (j0 + i < NE);  // warp-uniform
            int s = __shfl_sync(0xffffffffu, myidx, i);
            int dd = __shfl_sync(0xffffffffu, myidx, 16 + i);
            if (valid) {
                float ev = wst[i * 36 + lane];
                float hv = __ldg(g_h + (size_t)s * H + c0);
                acc += fmaxf(ev + hv, 0.f);
                bool last = (i == 15) || (j0 + i + 1 >= NE);
                int dn = last ? -1 : __shfl_sync(0xffffffffu, myidx, 16 + i + 1);
                if (last || dn != dd) {
                    atomicAdd(g_z + (size_t)dd * H + c0, acc);
                    acc = 0.f;
                }
            }
        }
        __syncwarp();  // strip consumed before next quarter overwrites it
    }
}

// ---------------- 128x128-tile fp32 GEMM: C = A @ W + b (proven R10) --------
// which==0: A=g_z -> C=g_t, relu, block0 zeroes BN stats
// which==1: A=g_t -> C=g_z2, no relu, fused BN sum/sumsq reduction
__global__ void __launch_bounds__(256) k_mlp(int which, const float* __restrict__ W,
                                             const float* __restrict__ bias) {
    const float* A = which ? g_t : g_z;
    float* C = which ? g_z2 : g_t;
    __shared__ float As[128 * 36];
    __shared__ float Ws[32 * 128];
    int tid = threadIdx.x;
    int tx = tid & 15;
    int ty = tid >> 4;
    int row0 = blockIdx.x * 128;

    if (which == 0 && blockIdx.x == 0 && tid < H) {
        g_colsum[tid] = 0.f;
        g_colsq[tid] = 0.f;
    }

    float acc[8][8];
#pragma unroll
    for (int j = 0; j < 8; j++)
#pragma unroll
        for (int c = 0; c < 8; c++) acc[j][c] = 0.f;

    for (int kt = 0; kt < 4; kt++) {
        for (int i = tid; i < 1024; i += 256) {
            int r = i >> 3, c4 = i & 7;
            int gr = row0 + r;
            float4 v = make_float4(0.f, 0.f, 0.f, 0.f);
            if (gr < NN) v = *(const float4*)(A + (size_t)gr * H + kt * 32 + c4 * 4);
            *(float4*)(As + r * 36 + c4 * 4) = v;
        }
        for (int i = tid; i < 1024; i += 256) {
            int k = i >> 5, c4 = i & 31;
            *(float4*)(Ws + k * H + c4 * 4) =
                *(const float4*)(W + (size_t)(kt * 32 + k) * H + c4 * 4);
        }
        __syncthreads();
#pragma unroll
        for (int k = 0; k < 32; k++) {
            float4 w0 = *(const float4*)(Ws + k * H + tx * 8);
            float4 w1 = *(const float4*)(Ws + k * H + tx * 8 + 4);
            float a[8];
#pragma unroll
            for (int j = 0; j < 8; j++) a[j] = As[(ty * 8 + j) * 36 + k];
#pragma unroll
            for (int j = 0; j < 8; j++) {
                acc[j][0] = fmaf(a[j], w0.x, acc[j][0]);
                acc[j][1] = fmaf(a[j], w0.y, acc[j][1]);
                acc[j][2] = fmaf(a[j], w0.z, acc[j][2]);
                acc[j][3] = fmaf(a[j], w0.w, acc[j][3]);
                acc[j][4] = fmaf(a[j], w1.x, acc[j][4]);
                acc[j][5] = fmaf(a[j], w1.y, acc[j][5]);
                acc[j][6] = fmaf(a[j], w1.z, acc[j][6]);
                acc[j][7] = fmaf(a[j], w1.w, acc[j][7]);
            }
        }
        __syncthreads();
    }

    float4 b0 = *(const float4*)(bias + tx * 8);
    float4 b1 = *(const float4*)(bias + tx * 8 + 4);

    if (which == 0) {
#pragma unroll
        for (int j = 0; j < 8; j++) {
            int gr = row0 + ty * 8 + j;
            if (gr < NN) {
                float4 o0, o1;
                o0.x = fmaxf(acc[j][0] + b0.x, 0.f);
                o0.y = fmaxf(acc[j][1] + b0.y, 0.f);
                o0.z = fmaxf(acc[j][2] + b0.z, 0.f);
                o0.w = fmaxf(acc[j][3] + b0.w, 0.f);
                o1.x = fmaxf(acc[j][4] + b1.x, 0.f);
                o1.y = fmaxf(acc[j][5] + b1.y, 0.f);
                o1.z = fmaxf(acc[j][6] + b1.z, 0.f);
                o1.w = fmaxf(acc[j][7] + b1.w, 0.f);
                *(float4*)(C + (size_t)gr * H + tx * 8) = o0;
                *(float4*)(C + (size_t)gr * H + tx * 8 + 4) = o1;
            }
        }
    } else {
        float psum[8], psq[8];
#pragma unroll
        for (int c = 0; c < 8; c++) { psum[c] = 0.f; psq[c] = 0.f; }
#pragma unroll
        for (int j = 0; j < 8; j++) {
            int gr = row0 + ty * 8 + j;
            if (gr < NN) {
                float o[8];
                o[0] = acc[j][0] + b0.x; o[1] = acc[j][1] + b0.y;
                o[2] = acc[j][2] + b0.z; o[3] = acc[j][3] + b0.w;
                o[4] = acc[j][4] + b1.x; o[5] = acc[j][5] + b1.y;
                o[6] = acc[j][6] + b1.z; o[7] = acc[j][7] + b1.w;
                *(float4*)(C + (size_t)gr * H + tx * 8) = *(float4*)&o[0];
                *(float4*)(C + (size_t)gr * H + tx * 8 + 4) = *(float4*)&o[4];
#pragma unroll
                for (int c = 0; c < 8; c++) {
                    psum[c] += o[c];
                    psq[c] = fmaf(o[c], o[c], psq[c]);
                }
            }
        }
        __syncthreads();
        float* Ssum = As;
        float* Ssq = Ws;
#pragma unroll
        for (int c = 0; c < 8; c++) {
            Ssum[ty * H + tx * 8 + c] = psum[c];
            Ssq[ty * H + tx * 8 + c] = psq[c];
        }
        __syncthreads();
        if (tid < H) {
            float s = 0.f, q = 0.f;
#pragma unroll
            for (int r = 0; r < 16; r++) {
                s += Ssum[r * H + tid];
                q += Ssq[r * H + tid];
            }
            atomicAdd(&g_colsum[tid], s);
            atomicAdd(&g_colsq[tid], q);
        }
    }
}

// ---------------- BN finalize + apply + relu + residual (fused) ------------
__global__ void __launch_bounds__(256) k_post(const float* __restrict__ gamma,
                                              const float* __restrict__ beta,
                                              float* __restrict__ dout,
                                              int use_dout) {
    __shared__ float s_sc[H], s_sh[H];
    int tid = threadIdx.x;
    if (tid < H) {
        float mu = g_colsum[tid] * (1.f / NN);
        float var = g_colsq[tid] * (1.f / NN) - mu * mu;
        float rs = rsqrtf(var + BN_EPS);
        float sc = rs * gamma[tid];
        s_sc[tid] = sc;
        s_sh[tid] = beta[tid] - mu * sc;
    }
    __syncthreads();
    int i = blockIdx.x * 256 + tid;
    if (i >= NN * H / 4) return;
    int c4 = i & 31;
    float4 z = ((const float4*)g_z2)[i];
    float4 sc = *(const float4*)(s_sc + c4 * 4);
    float4 sh = *(const float4*)(s_sh + c4 * 4);
    float4 hr = ((const float4*)g_h)[i];
    float4 o;
    o.x = fmaxf(fmaf(z.x, sc.x, sh.x), 0.f) + RES_SCALE * hr.x;
    o.y = fmaxf(fmaf(z.y, sc.y, sh.y), 0.f) + RES_SCALE * hr.y;
    o.z = fmaxf(fmaf(z.z, sc.z, sh.z), 0.f) + RES_SCALE * hr.z;
    o.w = fmaxf(fmaf(z.w, sc.w, sh.w), 0.f) + RES_SCALE * hr.w;
    if (use_dout) {
        ((float4*)dout)[i] = o;
    } else {
        ((float4*)g_h)[i] = o;
        ((float4*)g_z)[i] = o;  // pre-init next layer's aggregation target
    }
}

// ---------------- launch ----------------
extern "C" void kernel_launch(void* const* d_in, const int* in_sizes, int n_in,
                              void* d_out, int out_size) {
    const float* x = (const float*)d_in[0];
    const int* ei = (const int*)d_in[1];
    const float* ea = (const float*)d_in[2];
    const float* We = (const float*)d_in[3];
    const float* be = (const float*)d_in[4];
    const float* W1 = (const float*)d_in[5];
    const float* b1 = (const float*)d_in[6];
    const float* W2 = (const float*)d_in[7];
    const float* b2 = (const float*)d_in[8];
    const float* gamma = (const float*)d_in[9];
    const float* beta = (const float*)d_in[10];

    cudaFuncSetAttribute(k_eagg, cudaFuncAttributeMaxDynamicSharedMemorySize,
                         EAGG_SMEM);

    // launch index 3 (the profiled one) = first k_eagg
    k_prepinit<<<(NN * H / 4 + 255) / 256, 256>>>(x, ei);   // 0
    k_scan<<<(NN + 1023) / 1024, 1024>>>();                 // 1
    k_scat<<<(NE + 255) / 256, 256>>>();                    // 2

    for (int l = 0; l < 3; l++) {
        k_eagg<<<(NE + 127) / 128, 256, EAGG_SMEM>>>(ea, We + (size_t)l * ED * H,
                                                     be + (size_t)l * H);
        k_mlp<<<(NN + 127) / 128, 256>>>(0, W1 + (size_t)l * H * H,
                                         b1 + (size_t)l * H);
        k_mlp<<<(NN + 127) / 128, 256>>>(1, W2 + (size_t)l * H * H,
                                         b2 + (size_t)l * H);
        k_post<<<(NN * H / 4 + 255) / 256, 256>>>(gamma + (size_t)l * H,
                                                  beta + (size_t)l * H,
                                                  (float*)d_out, l == 2 ? 1 : 0);
    }
}

// round 16
// speedup vs baseline: 1.0571x; 1.0571x over previous
#include <cuda_runtime.h>

#define NN 50000
#define NE 800000
#define H 128
#define ED 32
#define BN_EPS 1e-5f
#define RES_SCALE 0.1f

// ---------------- scratch (device globals; allocation-free) ----------------
__device__ __align__(16) float g_h[NN * H];
__device__ __align__(16) float g_z[NN * H];
__device__ __align__(16) float g_z2[NN * H];
__device__ int g_src[NE];
__device__ int g_dstv[NE];
__device__ int g_eid[NE];
__device__ int g_ssort[NE];
__device__ int g_dsort[NE];
__device__ int g_cnt[NN];
__device__ int g_cursor[NN];
__device__ int g_ready;
__device__ int g_running;
__device__ __align__(16) float g_colsum[H];
__device__ __align__(16) float g_colsq[H];

__device__ __forceinline__ unsigned to_tf32(float f) {
    unsigned u;
    asm("cvt.rna.tf32.f32 %0, %1;" : "=r"(u) : "f"(f));
    return u;
}

#define MMA_TF32(D, A0, A1, A2, A3, B0, B1)                                   \
    asm("mma.sync.aligned.m16n8k8.row.col.f32.tf32.tf32.f32 "                 \
        "{%0,%1,%2,%3}, {%4,%5,%6,%7}, {%8,%9}, {%0,%1,%2,%3};"               \
        : "+f"(D[0]), "+f"(D[1]), "+f"(D[2]), "+f"(D[3])                      \
        : "r"(A0), "r"(A1), "r"(A2), "r"(A3), "r"(B0), "r"(B1))

// ---------------- fused CSR-count + h/z init --------------------------------
__global__ void k_prepinit(const float* __restrict__ x, const int* __restrict__ p) {
    int tid = threadIdx.x;
    int gid = blockIdx.x * 256 + tid;
    if (gid < NE) {
        int lane = tid & 31;
        int hi = p[2 * lane + 1] | p[2 * (lane + 32) + 1];
        bool i64 = (__ballot_sync(0xffffffffu, hi != 0) == 0);
        int s, d;
        if (i64) {
            const long long* q = (const long long*)p;
            s = (int)q[gid];
            d = (int)q[NE + gid];
        } else {
            s = p[gid];
            d = p[NE + gid];
        }
        g_src[gid] = s;
        g_dstv[gid] = d;
        atomicAdd(&g_cnt[d], 1);
    }
    if (gid < NN * H / 4) {
        float4 v = ((const float4*)x)[gid];
        ((float4*)g_h)[gid] = v;
        ((float4*)g_z)[gid] = v;
    }
}

// ---------------- single-pass decoupled chained scan ------------------------
__global__ void __launch_bounds__(1024) k_scan() {
    __shared__ int ws[32];
    __shared__ int sbase;
    int tid = threadIdx.x, lane = tid & 31, wid = tid >> 5;
    int i = blockIdx.x * 1024 + tid;
    int v = (i < NN) ? g_cnt[i] : 0;
    int s = v;
#pragma unroll
    for (int o = 1; o < 32; o <<= 1) {
        int t = __shfl_up_sync(0xffffffffu, s, o);
        if (lane >= o) s += t;
    }
    if (lane == 31) ws[wid] = s;
    __syncthreads();
    if (wid == 0) {
        int t = ws[lane];
#pragma unroll
        for (int o = 1; o < 32; o <<= 1) {
            int u = __shfl_up_sync(0xffffffffu, t, o);
            if (lane >= o) t += u;
        }
        ws[lane] = t;
    }
    __syncthreads();
    if (tid == 0) {
        int total = ws[31];
        int b = blockIdx.x;
        while (*(volatile int*)&g_ready != b) {
        }
        int base = *(volatile int*)&g_running;
        *(volatile int*)&g_running = base + total;
        __threadfence();
        *(volatile int*)&g_ready = b + 1;
        sbase = base;
    }
    __syncthreads();
    int excl = s - v + (wid > 0 ? ws[wid - 1] : 0) + sbase;
    if (i < NN) g_cursor[i] = excl;
}

// ---------------- light scatter: CSR index arrays only ----------------------
__global__ void k_scat() {
    int e = blockIdx.x * 256 + threadIdx.x;
    if (e == 0) {
        g_ready = 0;
        g_running = 0;
    }
    if (e < NN) g_cnt[e] = 0;
    if (e >= NE) return;
    int d = g_dstv[e];
    int pos = atomicAdd(&g_cursor[d], 1);
    g_eid[pos] = e;
    g_ssort[pos] = g_src[e];
    g_dsort[pos] = d;
}

// ---------------- fused edge-linear + aggregate (proven R15) ----------------
// block 0 also zeroes BN stats for this layer (stream-ordered: post(l-1) has
// already read them; k_mlp2 adds later in the stream).
#define EAGG_SMEM ((4608 + 32 * 132) * 4)
__global__ void __launch_bounds__(256, 6) k_eagg(const float* __restrict__ ea,
                                                 const float* __restrict__ We,
                                                 const float* __restrict__ be) {
    extern __shared__ float smf[];
    unsigned* As = (unsigned*)smf;          // phase 1: 128 x 36
    float* stage = smf;                     // phase 2: per-warp 16 x 36
    unsigned* Ws = (unsigned*)smf + 4608;   // 32 x 132, xor-swizzled

    int tid = threadIdx.x;
    int lane = tid & 31;
    int w = tid >> 5;
    size_t tile0 = (size_t)blockIdx.x * 128;

    if (blockIdx.x == 0 && tid < H) {
        g_colsum[tid] = 0.f;
        g_colsq[tid] = 0.f;
    }

    for (int i = tid; i < 1024; i += 256) {  // A: 128 CSR rows x 32 feats
        int r = i >> 3, c4 = i & 7;
        size_t j = tile0 + r;
        float4 v = make_float4(0.f, 0.f, 0.f, 0.f);
        if (j < NE) {
            int e = g_eid[j];
            v = *(const float4*)(ea + (size_t)e * ED + c4 * 4);
        }
        unsigned* dst = As + r * 36 + c4 * 4;
        dst[0] = to_tf32(v.x); dst[1] = to_tf32(v.y);
        dst[2] = to_tf32(v.z); dst[3] = to_tf32(v.w);
    }
    for (int i = tid; i < 1024; i += 256) {  // W: 32 x 128, swizzled store
        int k = i >> 5, c4 = i & 31;
        float4 v = *(const float4*)(We + (size_t)k * H + c4 * 4);
        unsigned* dst = Ws + k * 132 + ((c4 * 4) ^ ((k & 3) << 3));
        dst[0] = to_tf32(v.x); dst[1] = to_tf32(v.y);
        dst[2] = to_tf32(v.z); dst[3] = to_tf32(v.w);
    }
    __syncthreads();

    int g = lane >> 2;
    int r = lane & 3;
    int row_s = w * 16;

    unsigned a[4][4];
#pragma unroll
    for (int ks = 0; ks < 4; ks++) {
        int k0 = ks * 8;
        a[ks][0] = As[(row_s + g) * 36 + k0 + r];
        a[ks][1] = As[(row_s + g + 8) * 36 + k0 + r];
        a[ks][2] = As[(row_s + g) * 36 + k0 + r + 4];
        a[ks][3] = As[(row_s + g + 8) * 36 + k0 + r + 4];
    }
    __syncthreads();  // all As reads done; stage may now overwrite region0

    size_t j0 = tile0 + (size_t)w * 16;
    int myidx;
    if (lane < 16) {
        size_t j = j0 + lane;
        myidx = (j < NE) ? g_ssort[j] : 0;
    } else {
        size_t j = j0 + lane - 16;
        myidx = (j < NE) ? g_dsort[j] : -1;
    }

    float* wst = stage + w * 576;  // warp-private 16 x 36 strip

#pragma unroll
    for (int q = 0; q < 4; q++) {
#pragma unroll
        for (int ntl = 0; ntl < 4; ntl++) {
            int nt = q * 4 + ntl;
            int n0 = nt * 8;
            float d[4];
            float2 bb = *(const float2*)(be + n0 + 2 * r);
            d[0] = bb.x; d[1] = bb.y; d[2] = bb.x; d[3] = bb.y;
            int nsw = (n0 + g) ^ (r << 3);  // xor-unswizzle (k&3 == r)
#pragma unroll
            for (int ks = 0; ks < 4; ks++) {
                int k0 = ks * 8;
                unsigned b0 = Ws[(k0 + r) * 132 + nsw];
                unsigned b1 = Ws[(k0 + 4 + r) * 132 + nsw];
                MMA_TF32(d, a[ks][0], a[ks][1], a[ks][2], a[ks][3], b0, b1);
            }
            int lc = ntl * 8 + 2 * r;
            *(float2*)(wst + g * 36 + lc) = make_float2(d[0], d[1]);
            *(float2*)(wst + (g + 8) * 36 + lc) = make_float2(d[2], d[3]);
        }
        __syncwarp();

        int c0 = q * 32 + lane;
        float acc = 0.f;
#pragma unroll
        for (int i = 0; i < 16; i++) {
            bool valid = (j0 + i < NE);
            int s = __shfl_sync(0xffffffffu, myidx, i);
            int dd = __shfl_sync(0xffffffffu, myidx, 16 + i);
            if (valid) {
                float ev = wst[i * 36 + lane];
                float hv = __ldg(g_h + (size_t)s * H + c0);
                acc += fmaxf(ev + hv, 0.f);
                bool last = (i == 15) || (j0 + i + 1 >= NE);
                int dn = last ? -1 : __shfl_sync(0xffffffffu, myidx, 16 + i + 1);
                if (last || dn != dd) {
                    atomicAdd(g_z + (size_t)dd * H + c0, acc);
                    acc = 0.f;
                }
            }
        }
        __syncwarp();
    }
}

// ---------------- fused node MLP: z2 = relu(z@W1+b1)@W2 + b2 ----------------
// One 128-row block computes BOTH GEMMs: GEMM1 accumulates in registers
// (proven 8x8 microtile), stages T = relu(.+b1) into smem (full 128-wide
// row block), then GEMM2 reads A from smem T (no global A traffic).
// Epilogue stores g_z2 + fused BN partial sums.
// dyn smem: region0 = union{As 128x36 (GEMM1), T 128x132, BN stage} ; Ws 32x128
#define MLP2_SMEM ((128 * 132 + 32 * 128) * 4)
__global__ void __launch_bounds__(256) k_mlp2(const float* __restrict__ W1,
                                              const float* __restrict__ b1,
                                              const float* __restrict__ W2,
                                              const float* __restrict__ b2) {
    extern __shared__ float sm[];
    float* T = sm;                  // 128 x 132
    float* As = sm;                 // 128 x 36 (GEMM1 phases, overlaid)
    float* Ws = sm + 128 * 132;     // 32 x 128 (W chunk, both GEMMs)
    int tid = threadIdx.x;
    int tx = tid & 15;
    int ty = tid >> 4;
    int row0 = blockIdx.x * 128;

    float acc[8][8];
#pragma unroll
    for (int j = 0; j < 8; j++)
#pragma unroll
        for (int c = 0; c < 8; c++) acc[j][c] = 0.f;

    // ---- GEMM1: acc = Z_tile @ W1 ----
    for (int kt = 0; kt < 4; kt++) {
        for (int i = tid; i < 1024; i += 256) {
            int r = i >> 3, c4 = i & 7;
            int gr = row0 + r;
            float4 v = make_float4(0.f, 0.f, 0.f, 0.f);
            if (gr < NN) v = *(const float4*)(g_z + (size_t)gr * H + kt * 32 + c4 * 4);
            *(float4*)(As + r * 36 + c4 * 4) = v;
        }
        for (int i = tid; i < 1024; i += 256) {
            int k = i >> 5, c4 = i & 31;
            *(float4*)(Ws + k * H + c4 * 4) =
                *(const float4*)(W1 + (size_t)(kt * 32 + k) * H + c4 * 4);
        }
        __syncthreads();
#pragma unroll
        for (int k = 0; k < 32; k++) {
            float4 w0 = *(const float4*)(Ws + k * H + tx * 8);
            float4 w1 = *(const float4*)(Ws + k * H + tx * 8 + 4);
            float a[8];
#pragma unroll
            for (int j = 0; j < 8; j++) a[j] = As[(ty * 8 + j) * 36 + k];
#pragma unroll
            for (int j = 0; j < 8; j++) {
                acc[j][0] = fmaf(a[j], w0.x, acc[j][0]);
                acc[j][1] = fmaf(a[j], w0.y, acc[j][1]);
                acc[j][2] = fmaf(a[j], w0.z, acc[j][2]);
                acc[j][3] = fmaf(a[j], w0.w, acc[j][3]);
                acc[j][4] = fmaf(a[j], w1.x, acc[j][4]);
                acc[j][5] = fmaf(a[j], w1.y, acc[j][5]);
                acc[j][6] = fmaf(a[j], w1.z, acc[j][6]);
                acc[j][7] = fmaf(a[j], w1.w, acc[j][7]);
            }
        }
        __syncthreads();
    }

    // ---- stage T = relu(acc + b1) into smem (unconditionally, full tile) ----
    {
        float4 b0 = *(const float4*)(b1 + tx * 8);
        float4 b1v = *(const float4*)(b1 + tx * 8 + 4);
#pragma unroll
        for (int j = 0; j < 8; j++) {
            float o[8];
            o[0] = fmaxf(acc[j][0] + b0.x, 0.f);
            o[1] = fmaxf(acc[j][1] + b0.y, 0.f);
            o[2] = fmaxf(acc[j][2] + b0.z, 0.f);
            o[3] = fmaxf(acc[j][3] + b0.w, 0.f);
            o[4] = fmaxf(acc[j][4] + b1v.x, 0.f);
            o[5] = fmaxf(acc[j][5] + b1v.y, 0.f);
            o[6] = fmaxf(acc[j][6] + b1v.z, 0.f);
            o[7] = fmaxf(acc[j][7] + b1v.w, 0.f);
            *(float4*)(T + (ty * 8 + j) * 132 + tx * 8) = *(float4*)&o[0];
            *(float4*)(T + (ty * 8 + j) * 132 + tx * 8 + 4) = *(float4*)&o[4];
        }
    }
    __syncthreads();

    // ---- GEMM2: acc = T @ W2 (A from smem) ----
#pragma unroll
    for (int j = 0; j < 8; j++)
#pragma unroll
        for (int c = 0; c < 8; c++) acc[j][c] = 0.f;

    for (int kt = 0; kt < 4; kt++) {
        for (int i = tid; i < 1024; i += 256) {
            int k = i >> 5, c4 = i & 31;
            *(float4*)(Ws + k * H + c4 * 4) =
                *(const float4*)(W2 + (size_t)(kt * 32 + k) * H + c4 * 4);
        }
        __syncthreads();
#pragma unroll
        for (int k = 0; k < 32; k++) {
            float4 w0 = *(const float4*)(Ws + k * H + tx * 8);
            float4 w1 = *(const float4*)(Ws + k * H + tx * 8 + 4);
            float a[8];
#pragma unroll
            for (int j = 0; j < 8; j++) a[j] = T[(ty * 8 + j) * 132 + kt * 32 + k];
#pragma unroll
            for (int j = 0; j < 8; j++) {
                acc[j][0] = fmaf(a[j], w0.x, acc[j][0]);
                acc[j][1] = fmaf(a[j], w0.y, acc[j][1]);
                acc[j][2] = fmaf(a[j], w0.z, acc[j][2]);
                acc[j][3] = fmaf(a[j], w0.w, acc[j][3]);
                acc[j][4] = fmaf(a[j], w1.x, acc[j][4]);
                acc[j][5] = fmaf(a[j], w1.y, acc[j][5]);
                acc[j][6] = fmaf(a[j], w1.z, acc[j][6]);
                acc[j][7] = fmaf(a[j], w1.w, acc[j][7]);
            }
        }
        __syncthreads();
    }

    // ---- epilogue: store z2 + BN partial sums ----
    float4 b0 = *(const float4*)(b2 + tx * 8);
    float4 b1v = *(const float4*)(b2 + tx * 8 + 4);
    float psum[8], psq[8];
#pragma unroll
    for (int c = 0; c < 8; c++) { psum[c] = 0.f; psq[c] = 0.f; }
#pragma unroll
    for (int j = 0; j < 8; j++) {
        int gr = row0 + ty * 8 + j;
        if (gr < NN) {
            float o[8];
            o[0] = acc[j][0] + b0.x; o[1] = acc[j][1] + b0.y;
            o[2] = acc[j][2] + b0.z; o[3] = acc[j][3] + b0.w;
            o[4] = acc[j][4] + b1v.x; o[5] = acc[j][5] + b1v.y;
            o[6] = acc[j][6] + b1v.z; o[7] = acc[j][7] + b1v.w;
            *(float4*)(g_z2 + (size_t)gr * H + tx * 8) = *(float4*)&o[0];
            *(float4*)(g_z2 + (size_t)gr * H + tx * 8 + 4) = *(float4*)&o[4];
#pragma unroll
            for (int c = 0; c < 8; c++) {
                psum[c] += o[c];
                psq[c] = fmaf(o[c], o[c], psq[c]);
            }
        }
    }
    __syncthreads();  // done with T/Ws; reuse for BN reduction
    float* Ssum = sm;            // 16 x 128
    float* Ssq = sm + 16 * 128;  // 16 x 128
#pragma unroll
    for (int c = 0; c < 8; c++) {
        Ssum[ty * H + tx * 8 + c] = psum[c];
        Ssq[ty * H + tx * 8 + c] = psq[c];
    }
    __syncthreads();
    if (tid < H) {
        float s = 0.f, q = 0.f;
#pragma unroll
        for (int r = 0; r < 16; r++) {
            s += Ssum[r * H + tid];
            q += Ssq[r * H + tid];
        }
        atomicAdd(&g_colsum[tid], s);
        atomicAdd(&g_colsq[tid], q);
    }
}

// ---------------- BN finalize + apply + relu + residual (fused) ------------
__global__ void __launch_bounds__(256) k_post(const float* __restrict__ gamma,
                                              const float* __restrict__ beta,
                                              float* __restrict__ dout,
                                              int use_dout) {
    __shared__ float s_sc[H], s_sh[H];
    int tid = threadIdx.x;
    if (tid < H) {
        float mu = g_colsum[tid] * (1.f / NN);
        float var = g_colsq[tid] * (1.f / NN) - mu * mu;
        float rs = rsqrtf(var + BN_EPS);
        float sc = rs * gamma[tid];
        s_sc[tid] = sc;
        s_sh[tid] = beta[tid] - mu * sc;
    }
    __syncthreads();
    int i = blockIdx.x * 256 + tid;
    if (i >= NN * H / 4) return;
    int c4 = i & 31;
    float4 z = ((const float4*)g_z2)[i];
    float4 sc = *(const float4*)(s_sc + c4 * 4);
    float4 sh = *(const float4*)(s_sh + c4 * 4);
    float4 hr = ((const float4*)g_h)[i];
    float4 o;
    o.x = fmaxf(fmaf(z.x, sc.x, sh.x), 0.f) + RES_SCALE * hr.x;
    o.y = fmaxf(fmaf(z.y, sc.y, sh.y), 0.f) + RES_SCALE * hr.y;
    o.z = fmaxf(fmaf(z.z, sc.z, sh.z), 0.f) + RES_SCALE * hr.z;
    o.w = fmaxf(fmaf(z.w, sc.w, sh.w), 0.f) + RES_SCALE * hr.w;
    if (use_dout) {
        ((float4*)dout)[i] = o;
    } else {
        ((float4*)g_h)[i] = o;
        ((float4*)g_z)[i] = o;  // pre-init next layer's aggregation target
    }
}

// ---------------- launch ----------------
extern "C" void kernel_launch(void* const* d_in, const int* in_sizes, int n_in,
                              void* d_out, int out_size) {
    const float* x = (const float*)d_in[0];
    const int* ei = (const int*)d_in[1];
    const float* ea = (const float*)d_in[2];
    const float* We = (const float*)d_in[3];
    const float* be = (const float*)d_in[4];
    const float* W1 = (const float*)d_in[5];
    const float* b1 = (const float*)d_in[6];
    const float* W2 = (const float*)d_in[7];
    const float* b2 = (const float*)d_in[8];
    const float* gamma = (const float*)d_in[9];
    const float* beta = (const float*)d_in[10];

    cudaFuncSetAttribute(k_eagg, cudaFuncAttributeMaxDynamicSharedMemorySize,
                         EAGG_SMEM);
    cudaFuncSetAttribute(k_mlp2, cudaFuncAttributeMaxDynamicSharedMemorySize,
                         MLP2_SMEM);

    k_prepinit<<<(NN * H / 4 + 255) / 256, 256>>>(x, ei);   // 0
    k_scan<<<(NN + 1023) / 1024, 1024>>>();                 // 1
    k_scat<<<(NE + 255) / 256, 256>>>();                    // 2

    for (int l = 0; l < 3; l++) {
        k_eagg<<<(NE + 127) / 128, 256, EAGG_SMEM>>>(ea, We + (size_t)l * ED * H,
                                                     be + (size_t)l * H);
        k_mlp2<<<(NN + 127) / 128, 256, MLP2_SMEM>>>(
            W1 + (size_t)l * H * H, b1 + (size_t)l * H,
            W2 + (size_t)l * H * H, b2 + (size_t)l * H);
        k_post<<<(NN * H / 4 + 255) / 256, 256>>>(gamma + (size_t)l * H,
                                                  beta + (size_t)l * H,
                                                  (float*)d_out, l == 2 ? 1 : 0);
    }
}

// round 17
// speedup vs baseline: 1.2655x; 1.1972x over previous
#include <cuda_runtime.h>

#define NN 50000
#define NE 800000
#define H 128
#define ED 32
#define BN_EPS 1e-5f
#define RES_SCALE 0.1f

// ---------------- scratch (device globals; allocation-free) ----------------
__device__ __align__(16) float g_h[NN * H];
__device__ __align__(16) float g_z[NN * H];
__device__ __align__(16) float g_z2[NN * H];
__device__ int g_src[NE];
__device__ int g_dstv[NE];
__device__ int g_eid[NE];
__device__ int g_ssort[NE];
__device__ int g_dsort[NE];
__device__ int g_cnt[NN];
__device__ int g_cursor[NN];
__device__ int g_ready;
__device__ int g_running;
__device__ __align__(16) float g_colsum[H];
__device__ __align__(16) float g_colsq[H];

__device__ __forceinline__ unsigned to_tf32(float f) {
    unsigned u;
    asm("cvt.rna.tf32.f32 %0, %1;" : "=r"(u) : "f"(f));
    return u;
}

#define MMA_TF32(D, A0, A1, A2, A3, B0, B1)                                   \
    asm("mma.sync.aligned.m16n8k8.row.col.f32.tf32.tf32.f32 "                 \
        "{%0,%1,%2,%3}, {%4,%5,%6,%7}, {%8,%9}, {%0,%1,%2,%3};"               \
        : "+f"(D[0]), "+f"(D[1]), "+f"(D[2]), "+f"(D[3])                      \
        : "r"(A0), "r"(A1), "r"(A2), "r"(A3), "r"(B0), "r"(B1))

// ---------------- fused CSR-count + h/z init --------------------------------
__global__ void k_prepinit(const float* __restrict__ x, const int* __restrict__ p) {
    int tid = threadIdx.x;
    int gid = blockIdx.x * 256 + tid;
    if (gid < NE) {
        int lane = tid & 31;
        int hi = p[2 * lane + 1] | p[2 * (lane + 32) + 1];
        bool i64 = (__ballot_sync(0xffffffffu, hi != 0) == 0);
        int s, d;
        if (i64) {
            const long long* q = (const long long*)p;
            s = (int)q[gid];
            d = (int)q[NE + gid];
        } else {
            s = p[gid];
            d = p[NE + gid];
        }
        g_src[gid] = s;
        g_dstv[gid] = d;
        atomicAdd(&g_cnt[d], 1);
    }
    if (gid < NN * H / 4) {
        float4 v = ((const float4*)x)[gid];
        ((float4*)g_h)[gid] = v;
        ((float4*)g_z)[gid] = v;
    }
}

// ---------------- single-pass decoupled chained scan ------------------------
__global__ void __launch_bounds__(1024) k_scan() {
    __shared__ int ws[32];
    __shared__ int sbase;
    int tid = threadIdx.x, lane = tid & 31, wid = tid >> 5;
    int i = blockIdx.x * 1024 + tid;
    int v = (i < NN) ? g_cnt[i] : 0;
    int s = v;
#pragma unroll
    for (int o = 1; o < 32; o <<= 1) {
        int t = __shfl_up_sync(0xffffffffu, s, o);
        if (lane >= o) s += t;
    }
    if (lane == 31) ws[wid] = s;
    __syncthreads();
    if (wid == 0) {
        int t = ws[lane];
#pragma unroll
        for (int o = 1; o < 32; o <<= 1) {
            int u = __shfl_up_sync(0xffffffffu, t, o);
            if (lane >= o) t += u;
        }
        ws[lane] = t;
    }
    __syncthreads();
    if (tid == 0) {
        int total = ws[31];
        int b = blockIdx.x;
        while (*(volatile int*)&g_ready != b) {
        }
        int base = *(volatile int*)&g_running;
        *(volatile int*)&g_running = base + total;
        __threadfence();
        *(volatile int*)&g_ready = b + 1;
        sbase = base;
    }
    __syncthreads();
    int excl = s - v + (wid > 0 ? ws[wid - 1] : 0) + sbase;
    if (i < NN) g_cursor[i] = excl;
}

// ---------------- light scatter: CSR index arrays only ----------------------
__global__ void k_scat() {
    int e = blockIdx.x * 256 + threadIdx.x;
    if (e == 0) {
        g_ready = 0;
        g_running = 0;
    }
    if (e < NN) g_cnt[e] = 0;
    if (e >= NE) return;
    int d = g_dstv[e];
    int pos = atomicAdd(&g_cursor[d], 1);
    g_eid[pos] = e;
    g_ssort[pos] = g_src[e];
    g_dsort[pos] = d;
}

// ---------------- fused edge-linear + aggregate ------------------------------
// Quarter-staged, conflict-free, PHASE-SPLIT aggregation:
//  pass 1 (branch-free): m[i] = relu(elin + h[src]) for 16 edges -> MLP 16
//  pass 2: run-flush with per-strip precomputed boundary mask (ballot),
//          warp-uniform flush branches, no per-iter dn shuffle.
#define EAGG_SMEM ((4608 + 32 * 132) * 4)
__global__ void __launch_bounds__(256, 5) k_eagg(const float* __restrict__ ea,
                                                 const float* __restrict__ We,
                                                 const float* __restrict__ be) {
    extern __shared__ float smf[];
    unsigned* As = (unsigned*)smf;          // phase 1: 128 x 36
    float* stage = smf;                     // phase 2: per-warp 16 x 36
    unsigned* Ws = (unsigned*)smf + 4608;   // 32 x 132, xor-swizzled

    int tid = threadIdx.x;
    int lane = tid & 31;
    int w = tid >> 5;
    size_t tile0 = (size_t)blockIdx.x * 128;

    if (blockIdx.x == 0 && tid < H) {
        g_colsum[tid] = 0.f;
        g_colsq[tid] = 0.f;
    }

    for (int i = tid; i < 1024; i += 256) {  // A: 128 CSR rows x 32 feats
        int r = i >> 3, c4 = i & 7;
        size_t j = tile0 + r;
        float4 v = make_float4(0.f, 0.f, 0.f, 0.f);
        if (j < NE) {
            int e = g_eid[j];
            v = *(const float4*)(ea + (size_t)e * ED + c4 * 4);
        }
        unsigned* dst = As + r * 36 + c4 * 4;
        dst[0] = to_tf32(v.x); dst[1] = to_tf32(v.y);
        dst[2] = to_tf32(v.z); dst[3] = to_tf32(v.w);
    }
    for (int i = tid; i < 1024; i += 256) {  // W: 32 x 128, swizzled store
        int k = i >> 5, c4 = i & 31;
        float4 v = *(const float4*)(We + (size_t)k * H + c4 * 4);
        unsigned* dst = Ws + k * 132 + ((c4 * 4) ^ ((k & 3) << 3));
        dst[0] = to_tf32(v.x); dst[1] = to_tf32(v.y);
        dst[2] = to_tf32(v.z); dst[3] = to_tf32(v.w);
    }
    __syncthreads();

    int g = lane >> 2;
    int r = lane & 3;
    int row_s = w * 16;

    unsigned a[4][4];
#pragma unroll
    for (int ks = 0; ks < 4; ks++) {
        int k0 = ks * 8;
        a[ks][0] = As[(row_s + g) * 36 + k0 + r];
        a[ks][1] = As[(row_s + g + 8) * 36 + k0 + r];
        a[ks][2] = As[(row_s + g) * 36 + k0 + r + 4];
        a[ks][3] = As[(row_s + g + 8) * 36 + k0 + r + 4];
    }
    __syncthreads();  // all As reads done; stage may now overwrite region0

    // index preload: lanes 0-15 -> ssort, lanes 16-31 -> dsort (-1 invalid)
    size_t j0 = tile0 + (size_t)w * 16;
    int myidx;
    if (lane < 16) {
        size_t j = j0 + lane;
        myidx = (j < NE) ? g_ssort[j] : 0;
    } else {
        size_t j = j0 + lane - 16;
        myidx = (j < NE) ? g_dsort[j] : -1;
    }

    // per-strip masks (computed once): validity + run boundaries
    int nxt = __shfl_down_sync(0xffffffffu, myidx, 1);
    bool isv = (lane >= 16) && (myidx != -1);
    bool bnd = isv && ((lane == 31) || (nxt != myidx));
    unsigned vmask = __ballot_sync(0xffffffffu, isv) >> 16;
    unsigned bmask = __ballot_sync(0xffffffffu, bnd) >> 16;

    float* wst = stage + w * 576;  // warp-private 16 x 36 strip

#pragma unroll
    for (int q = 0; q < 4; q++) {
        // compute 4 nt fragments for this column quarter, stage warp-locally
#pragma unroll
        for (int ntl = 0; ntl < 4; ntl++) {
            int nt = q * 4 + ntl;
            int n0 = nt * 8;
            float d[4];
            float2 bb = *(const float2*)(be + n0 + 2 * r);
            d[0] = bb.x; d[1] = bb.y; d[2] = bb.x; d[3] = bb.y;
            int nsw = (n0 + g) ^ (r << 3);  // xor-unswizzle (k&3 == r)
#pragma unroll
            for (int ks = 0; ks < 4; ks++) {
                int k0 = ks * 8;
                unsigned b0 = Ws[(k0 + r) * 132 + nsw];
                unsigned b1 = Ws[(k0 + 4 + r) * 132 + nsw];
                MMA_TF32(d, a[ks][0], a[ks][1], a[ks][2], a[ks][3], b0, b1);
            }
            int lc = ntl * 8 + 2 * r;
            *(float2*)(wst + g * 36 + lc) = make_float2(d[0], d[1]);
            *(float2*)(wst + (g + 8) * 36 + lc) = make_float2(d[2], d[3]);
        }
        __syncwarp();

        int c0 = q * 32 + lane;

        // pass 1: branch-free batched loads -> m[16]
        float m[16];
#pragma unroll
        for (int i = 0; i < 16; i++) {
            int s = __shfl_sync(0xffffffffu, myidx, i);
            float ev = wst[i * 36 + lane];
            float hv = __ldg(g_h + (size_t)s * H + c0);
            float t = fmaxf(ev + hv, 0.f);
            m[i] = (vmask >> i & 1u) ? t : 0.f;
        }

        // pass 2: run flush (bmask is warp-uniform -> uniform branches)
        float acc = 0.f;
#pragma unroll
        for (int i = 0; i < 16; i++) {
            acc += m[i];
            if (bmask >> i & 1u) {
                int dd = __shfl_sync(0xffffffffu, myidx, 16 + i);
                atomicAdd(g_z + (size_t)dd * H + c0, acc);
                acc = 0.f;
            }
        }
        __syncwarp();  // strip consumed before next quarter overwrites it
    }
}

// ---------------- fused node MLP: z2 = relu(z@W1+b1)@W2 + b2 (proven R16) ---
#define MLP2_SMEM ((128 * 132 + 32 * 128) * 4)
__global__ void __launch_bounds__(256) k_mlp2(const float* __restrict__ W1,
                                              const float* __restrict__ b1,
                                              const float* __restrict__ W2,
                                              const float* __restrict__ b2) {
    extern __shared__ float sm[];
    float* T = sm;                  // 128 x 132
    float* As = sm;                 // 128 x 36 (GEMM1 phases, overlaid)
    float* Ws = sm + 128 * 132;     // 32 x 128 (W chunk, both GEMMs)
    int tid = threadIdx.x;
    int tx = tid & 15;
    int ty = tid >> 4;
    int row0 = blockIdx.x * 128;

    float acc[8][8];
#pragma unroll
    for (int j = 0; j < 8; j++)
#pragma unroll
        for (int c = 0; c < 8; c++) acc[j][c] = 0.f;

    // ---- GEMM1: acc = Z_tile @ W1 ----
    for (int kt = 0; kt < 4; kt++) {
        for (int i = tid; i < 1024; i += 256) {
            int r = i >> 3, c4 = i & 7;
            int gr = row0 + r;
            float4 v = make_float4(0.f, 0.f, 0.f, 0.f);
            if (gr < NN) v = *(const float4*)(g_z + (size_t)gr * H + kt * 32 + c4 * 4);
            *(float4*)(As + r * 36 + c4 * 4) = v;
        }
        for (int i = tid; i < 1024; i += 256) {
            int k = i >> 5, c4 = i & 31;
            *(float4*)(Ws + k * H + c4 * 4) =
                *(const float4*)(W1 + (size_t)(kt * 32 + k) * H + c4 * 4);
        }
        __syncthreads();
#pragma unroll
        for (int k = 0; k < 32; k++) {
            float4 w0 = *(const float4*)(Ws + k * H + tx * 8);
            float4 w1 = *(const float4*)(Ws + k * H + tx * 8 + 4);
            float a[8];
#pragma unroll
            for (int j = 0; j < 8; j++) a[j] = As[(ty * 8 + j) * 36 + k];
#pragma unroll
            for (int j = 0; j < 8; j++) {
                acc[j][0] = fmaf(a[j], w0.x, acc[j][0]);
                acc[j][1] = fmaf(a[j], w0.y, acc[j][1]);
                acc[j][2] = fmaf(a[j], w0.z, acc[j][2]);
                acc[j][3] = fmaf(a[j], w0.w, acc[j][3]);
                acc[j][4] = fmaf(a[j], w1.x, acc[j][4]);
                acc[j][5] = fmaf(a[j], w1.y, acc[j][5]);
                acc[j][6] = fmaf(a[j], w1.z, acc[j][6]);
                acc[j][7] = fmaf(a[j], w1.w, acc[j][7]);
            }
        }
        __syncthreads();
    }

    // ---- stage T = relu(acc + b1) into smem ----
    {
        float4 b0 = *(const float4*)(b1 + tx * 8);
        float4 b1v = *(const float4*)(b1 + tx * 8 + 4);
#pragma unroll
        for (int j = 0; j < 8; j++) {
            float o[8];
            o[0] = fmaxf(acc[j][0] + b0.x, 0.f);
            o[1] = fmaxf(acc[j][1] + b0.y, 0.f);
            o[2] = fmaxf(acc[j][2] + b0.z, 0.f);
            o[3] = fmaxf(acc[j][3] + b0.w, 0.f);
            o[4] = fmaxf(acc[j][4] + b1v.x, 0.f);
            o[5] = fmaxf(acc[j][5] + b1v.y, 0.f);
            o[6] = fmaxf(acc[j][6] + b1v.z, 0.f);
            o[7] = fmaxf(acc[j][7] + b1v.w, 0.f);
            *(float4*)(T + (ty * 8 + j) * 132 + tx * 8) = *(float4*)&o[0];
            *(float4*)(T + (ty * 8 + j) * 132 + tx * 8 + 4) = *(float4*)&o[4];
        }
    }
    __syncthreads();

    // ---- GEMM2: acc = T @ W2 (A from smem) ----
#pragma unroll
    for (int j = 0; j < 8; j++)
#pragma unroll
        for (int c = 0; c < 8; c++) acc[j][c] = 0.f;

    for (int kt = 0; kt < 4; kt++) {
        for (int i = tid; i < 1024; i += 256) {
            int k = i >> 5, c4 = i & 31;
            *(float4*)(Ws + k * H + c4 * 4) =
                *(const float4*)(W2 + (size_t)(kt * 32 + k) * H + c4 * 4);
        }
        __syncthreads();
#pragma unroll
        for (int k = 0; k < 32; k++) {
            float4 w0 = *(const float4*)(Ws + k * H + tx * 8);
            float4 w1 = *(const float4*)(Ws + k * H + tx * 8 + 4);
            float a[8];
#pragma unroll
            for (int j = 0; j < 8; j++) a[j] = T[(ty * 8 + j) * 132 + kt * 32 + k];
#pragma unroll
            for (int j = 0; j < 8; j++) {
                acc[j][0] = fmaf(a[j], w0.x, acc[j][0]);
                acc[j][1] = fmaf(a[j], w0.y, acc[j][1]);
                acc[j][2] = fmaf(a[j], w0.z, acc[j][2]);
                acc[j][3] = fmaf(a[j], w0.w, acc[j][3]);
                acc[j][4] = fmaf(a[j], w1.x, acc[j][4]);
                acc[j][5] = fmaf(a[j], w1.y, acc[j][5]);
                acc[j][6] = fmaf(a[j], w1.z, acc[j][6]);
                acc[j][7] = fmaf(a[j], w1.w, acc[j][7]);
            }
        }
        __syncthreads();
    }

    // ---- epilogue: store z2 + BN partial sums ----
    float4 b0 = *(const float4*)(b2 + tx * 8);
    float4 b1v = *(const float4*)(b2 + tx * 8 + 4);
    float psum[8], psq[8];
#pragma unroll
    for (int c = 0; c < 8; c++) { psum[c] = 0.f; psq[c] = 0.f; }
#pragma unroll
    for (int j = 0; j < 8; j++) {
        int gr = row0 + ty * 8 + j;
        if (gr < NN) {
            float o[8];
            o[0] = acc[j][0] + b0.x; o[1] = acc[j][1] + b0.y;
            o[2] = acc[j][2] + b0.z; o[3] = acc[j][3] + b0.w;
            o[4] = acc[j][4] + b1v.x; o[5] = acc[j][5] + b1v.y;
            o[6] = acc[j][6] + b1v.z; o[7] = acc[j][7] + b1v.w;
            *(float4*)(g_z2 + (size_t)gr * H + tx * 8) = *(float4*)&o[0];
            *(float4*)(g_z2 + (size_t)gr * H + tx * 8 + 4) = *(float4*)&o[4];
#pragma unroll
            for (int c = 0; c < 8; c++) {
                psum[c] += o[c];
                psq[c] = fmaf(o[c], o[c], psq[c]);
            }
        }
    }
    __syncthreads();  // done with T/Ws; reuse for BN reduction
    float* Ssum = sm;            // 16 x 128
    float* Ssq = sm + 16 * 128;  // 16 x 128
#pragma unroll
    for (int c = 0; c < 8; c++) {
        Ssum[ty * H + tx * 8 + c] = psum[c];
        Ssq[ty * H + tx * 8 + c] = psq[c];
    }
    __syncthreads();
    if (tid < H) {
        float s = 0.f, q = 0.f;
#pragma unroll
        for (int r = 0; r < 16; r++) {
            s += Ssum[r * H + tid];
            q += Ssq[r * H + tid];
        }
        atomicAdd(&g_colsum[tid], s);
        atomicAdd(&g_colsq[tid], q);
    }
}

// ---------------- BN finalize + apply + relu + residual (fused) ------------
__global__ void __launch_bounds__(256) k_post(const float* __restrict__ gamma,
                                              const float* __restrict__ beta,
                                              float* __restrict__ dout,
                                              int use_dout) {
    __shared__ float s_sc[H], s_sh[H];
    int tid = threadIdx.x;
    if (tid < H) {
        float mu = g_colsum[tid] * (1.f / NN);
        float var = g_colsq[tid] * (1.f / NN) - mu * mu;
        float rs = rsqrtf(var + BN_EPS);
        float sc = rs * gamma[tid];
        s_sc[tid] = sc;
        s_sh[tid] = beta[tid] - mu * sc;
    }
    __syncthreads();
    int i = blockIdx.x * 256 + tid;
    if (i >= NN * H / 4) return;
    int c4 = i & 31;
    float4 z = ((const float4*)g_z2)[i];
    float4 sc = *(const float4*)(s_sc + c4 * 4);
    float4 sh = *(const float4*)(s_sh + c4 * 4);
    float4 hr = ((const float4*)g_h)[i];
    float4 o;
    o.x = fmaxf(fmaf(z.x, sc.x, sh.x), 0.f) + RES_SCALE * hr.x;
    o.y = fmaxf(fmaf(z.y, sc.y, sh.y), 0.f) + RES_SCALE * hr.y;
    o.z = fmaxf(fmaf(z.z, sc.z, sh.z), 0.f) + RES_SCALE * hr.z;
    o.w = fmaxf(fmaf(z.w, sc.w, sh.w), 0.f) + RES_SCALE * hr.w;
    if (use_dout) {
        ((float4*)dout)[i] = o;
    } else {
        ((float4*)g_h)[i] = o;
        ((float4*)g_z)[i] = o;  // pre-init next layer's aggregation target
    }
}

// ---------------- launch ----------------
extern "C" void kernel_launch(void* const* d_in, const int* in_sizes, int n_in,
                              void* d_out, int out_size) {
    const float* x = (const float*)d_in[0];
    const int* ei = (const int*)d_in[1];
    const float* ea = (const float*)d_in[2];
    const float* We = (const float*)d_in[3];
    const float* be = (const float*)d_in[4];
    const float* W1 = (const float*)d_in[5];
    const float* b1 = (const float*)d_in[6];
    const float* W2 = (const float*)d_in[7];
    const float* b2 = (const float*)d_in[8];
    const float* gamma = (const float*)d_in[9];
    const float* beta = (const float*)d_in[10];

    cudaFuncSetAttribute(k_eagg, cudaFuncAttributeMaxDynamicSharedMemorySize,
                         EAGG_SMEM);
    cudaFuncSetAttribute(k_mlp2, cudaFuncAttributeMaxDynamicSharedMemorySize,
                         MLP2_SMEM);

    k_prepinit<<<(NN * H / 4 + 255) / 256, 256>>>(x, ei);   // 0
    k_scan<<<(NN + 1023) / 1024, 1024>>>();                 // 1
    k_scat<<<(NE + 255) / 256, 256>>>();                    // 2

    for (int l = 0; l < 3; l++) {
        k_eagg<<<(NE + 127) / 128, 256, EAGG_SMEM>>>(ea, We + (size_t)l * ED * H,
                                                     be + (size_t)l * H);
        k_mlp2<<<(NN + 127) / 128, 256, MLP2_SMEM>>>(
            W1 + (size_t)l * H * H, b1 + (size_t)l * H,
            W2 + (size_t)l * H * H, b2 + (size_t)l * H);
        k_post<<<(NN * H / 4 + 255) / 256, 256>>>(gamma + (size_t)l * H,
                                                  beta + (size_t)l * H,
                                                  (float*)d_out, l == 2 ? 1 : 0);
    }
}